// round 2
// baseline (speedup 1.0000x reference)
#include <cuda_runtime.h>

// Problem constants (fixed by the dataset)
#define B_   64
#define C_   8
#define H_   256
#define W_   256
#define N_   200
#define NUM_CLASSES 3
#define NTGT (B_ * N_)                 // 12800
#define HW   (H_ * W_)                 // 65536
#define NELEM (NTGT * C_)              // 102400

#define THREADS 512
#define BLOCKS  (NELEM / THREADS)      // 200 (exact)
#define NWARPS  (THREADS / 32)         // 16

// Per-block partials (overwritten every launch) + arrival counter (reset by last block).
__device__ float4 g_part[BLOCKS];
__device__ unsigned int g_count;

__device__ __forceinline__ float softplus_f(float x) {
    // log(1+exp(x)) stable: max(x,0) + log1p(exp(-|x|))  (== jax.nn.softplus)
    return fmaxf(x, 0.0f) + log1pf(expf(-fabsf(x)));
}

__global__ void __launch_bounds__(THREADS)
yolo_loss_kernel(const float* __restrict__ pred,
                 const float* __restrict__ targets,
                 float* __restrict__ out)
{
    const int tid  = threadIdx.x;
    const int idx  = blockIdx.x * THREADS + tid;   // element = target*8 + channel
    const int g    = idx >> 3;                     // target index
    const int c    = idx & 7;                      // channel 0..7
    const int lane = tid & 31;
    const int base8 = lane & ~7;                   // first lane of this target's 8-lane group

    const unsigned full = 0xFFFFFFFFu;

    // ---- coalesced target load: lane (base8+j) loads targets[g*5+j], j<5 ----
    float tval = 0.0f;
    if (c < 5) tval = __ldg(targets + (size_t)g * 5 + c);
    const float cls_id = __shfl_sync(full, tval, base8 + 0);
    const float c0     = __shfl_sync(full, tval, base8 + 1);
    const float c1     = __shfl_sync(full, tval, base8 + 2);
    const float c2     = __shfl_sync(full, tval, base8 + 3);
    const float c3     = __shfl_sync(full, tval, base8 + 4);

    const bool valid = (cls_id >= 0.0f) && ((c0 + c1 + c2 + c3) > 0.0f);
    const int xpix = (int)(c0 * (float)W_);        // fp32 mul then trunc == astype(int32)
    const int ypix = (int)(c1 * (float)H_);
    const bool inb = (xpix >= 0) && (xpix < W_) && (ypix >= 0) && (ypix < H_);

    float bbox_t = 0.0f, obj_t = 0.0f, cls_t = 0.0f;

    if (valid && inb) {
        const int xs = min(max(xpix, 0), W_ - 1);
        const int ys = min(max(ypix, 0), H_ - 1);
        const int b  = g / N_;

        const float p = __ldg(pred + (size_t)b * (C_ * HW) + (size_t)c * HW
                                   + (size_t)ys * W_ + xs);

        if (c < 4) {
            const float coord = (c == 0) ? c0 : (c == 1) ? c1 : (c == 2) ? c2 : c3;
            const float d = p - coord;
            bbox_t = 0.25f * d * d;                // mean over 4 channels
        } else if (c == 4) {
            obj_t = softplus_f(p) - p;             // bce(p, 1)
        } else {
            const int k = (int)fmaxf(cls_id, 0.0f);
            const float z = ((c - 5) == k) ? 1.0f : 0.0f;
            cls_t = (softplus_f(p) - p * z) * (1.0f / (float)NUM_CLASSES);
        }
    }

    // ---- warp reduction ----
#pragma unroll
    for (int off = 16; off > 0; off >>= 1) {
        bbox_t += __shfl_down_sync(full, bbox_t, off);
        obj_t  += __shfl_down_sync(full, obj_t,  off);
        cls_t  += __shfl_down_sync(full, cls_t,  off);
    }

    __shared__ float s_b[NWARPS], s_o[NWARPS], s_c[NWARPS];
    const int warp = tid >> 5;
    if (lane == 0) { s_b[warp] = bbox_t; s_o[warp] = obj_t; s_c[warp] = cls_t; }
    __syncthreads();

    __shared__ bool is_last;
    if (tid == 0) {
        float bb = 0.f, oo = 0.f, cc = 0.f;
#pragma unroll
        for (int w = 0; w < NWARPS; w++) { bb += s_b[w]; oo += s_o[w]; cc += s_c[w]; }
        g_part[blockIdx.x] = make_float4(bb, oo, cc, 0.0f);
        __threadfence();
        const unsigned v = atomicAdd(&g_count, 1u);
        is_last = (v == (unsigned)(BLOCKS - 1));
    }
    __syncthreads();

    // ---- last block: reduce per-block partials in fp64, write out, reset counter ----
    if (is_last) {
        __threadfence();   // acquire: see all blocks' g_part stores

        double bb = 0.0, oo = 0.0, cc = 0.0;
        if (tid < BLOCKS) {
            const float4 v = g_part[tid];
            bb = (double)v.x; oo = (double)v.y; cc = (double)v.z;
        }
#pragma unroll
        for (int off = 16; off > 0; off >>= 1) {
            bb += __shfl_down_sync(full, bb, off);
            oo += __shfl_down_sync(full, oo, off);
            cc += __shfl_down_sync(full, cc, off);
        }
        __shared__ double d_b[NWARPS], d_o[NWARPS], d_c[NWARPS];
        if (lane == 0) { d_b[warp] = bb; d_o[warp] = oo; d_c[warp] = cc; }
        __syncthreads();
        if (tid == 0) {
            double B = 0.0, O = 0.0, Cc = 0.0;
#pragma unroll
            for (int w = 0; w < NWARPS; w++) { B += d_b[w]; O += d_o[w]; Cc += d_c[w]; }
            const double total = 0.05 * B + 1.0 * O + 0.5 * Cc;
            out[0] = (float)total;
            out[1] = (float)B;
            out[2] = (float)O;
            out[3] = (float)Cc;
            g_count = 0u;      // reset for next graph replay
            __threadfence();
        }
    }
}

extern "C" void kernel_launch(void* const* d_in, const int* in_sizes, int n_in,
                              void* d_out, int out_size)
{
    const float* pred    = (const float*)d_in[0];
    const float* targets = (const float*)d_in[1];
    float* out = (float*)d_out;
    (void)in_sizes; (void)n_in; (void)out_size;

    yolo_loss_kernel<<<BLOCKS, THREADS>>>(pred, targets, out);
}

// round 3
// speedup vs baseline: 1.1797x; 1.1797x over previous
#include <cuda_runtime.h>

// Problem constants (fixed by the dataset)
#define B_   64
#define C_   8
#define H_   256
#define W_   256
#define N_   200
#define NUM_CLASSES 3
#define NTGT (B_ * N_)                 // 12800
#define HW   (H_ * W_)                 // 65536

#define THREADS 128
#define BLOCKS  (NTGT / THREADS)       // 100 (exact)
#define NWARPS  (THREADS / 32)         // 4

// Per-block partials (plain stores, overwritten every launch) + arrival counter
// (reset by last block -> deterministic under graph replay).
__device__ float4 g_part[BLOCKS];
__device__ unsigned int g_count;

__device__ __forceinline__ float softplus_f(float x) {
    // log(1+exp(x)) stable: max(x,0) + log1p(exp(-|x|))  (== jax.nn.softplus)
    return fmaxf(x, 0.0f) + log1pf(expf(-fabsf(x)));
}

__global__ void __launch_bounds__(THREADS)
yolo_loss_kernel(const float* __restrict__ pred,
                 const float* __restrict__ targets,
                 float* __restrict__ out)
{
    const int tid = threadIdx.x;
    const int g   = blockIdx.x * THREADS + tid;    // target index (always < NTGT)

    float bbox_t = 0.0f, obj_t = 0.0f, cls_t = 0.0f;

    {
        const float* t = targets + (size_t)g * 5;
        const float cls_id = __ldg(t + 0);
        const float c0 = __ldg(t + 1), c1 = __ldg(t + 2);
        const float c2 = __ldg(t + 3), c3 = __ldg(t + 4);

        const bool valid = (cls_id >= 0.0f) && ((c0 + c1 + c2 + c3) > 0.0f);
        const int xpix = (int)(c0 * (float)W_);    // fp32 mul then trunc == astype(int32)
        const int ypix = (int)(c1 * (float)H_);
        const bool inb = (xpix >= 0) && (xpix < W_) && (ypix >= 0) && (ypix < H_);

        if (valid && inb) {
            const int xs = min(max(xpix, 0), W_ - 1);
            const int ys = min(max(ypix, 0), H_ - 1);
            const int b  = g / N_;

            const size_t base = (size_t)b * (C_ * HW) + (size_t)ys * W_ + xs;

            // 8 independent scattered loads — batched for MLP=8
            float p[C_];
#pragma unroll
            for (int c = 0; c < C_; c++)
                p[c] = __ldg(pred + base + (size_t)c * HW);

            const float d0 = p[0] - c0, d1 = p[1] - c1, d2 = p[2] - c2, d3 = p[3] - c3;
            bbox_t = 0.25f * (d0 * d0 + d1 * d1 + d2 * d2 + d3 * d3);

            obj_t = softplus_f(p[4]) - p[4];       // bce(p4, 1)

            const int k = (int)fmaxf(cls_id, 0.0f);
            float cs = 0.0f;
#pragma unroll
            for (int j = 0; j < NUM_CLASSES; j++) {
                const float lg = p[5 + j];
                cs += softplus_f(lg) - ((j == k) ? lg : 0.0f);
            }
            cls_t = cs * (1.0f / (float)NUM_CLASSES);
        }
    }

    // ---- block reduction ----
    const unsigned full = 0xFFFFFFFFu;
#pragma unroll
    for (int off = 16; off > 0; off >>= 1) {
        bbox_t += __shfl_down_sync(full, bbox_t, off);
        obj_t  += __shfl_down_sync(full, obj_t,  off);
        cls_t  += __shfl_down_sync(full, cls_t,  off);
    }

    __shared__ float s_b[NWARPS], s_o[NWARPS], s_c[NWARPS];
    const int warp = tid >> 5, lane = tid & 31;
    if (lane == 0) { s_b[warp] = bbox_t; s_o[warp] = obj_t; s_c[warp] = cls_t; }
    __syncthreads();

    __shared__ bool is_last;
    if (tid == 0) {
        float bb = s_b[0] + s_b[1] + s_b[2] + s_b[3];
        float oo = s_o[0] + s_o[1] + s_o[2] + s_o[3];
        float cc = s_c[0] + s_c[1] + s_c[2] + s_c[3];
        g_part[blockIdx.x] = make_float4(bb, oo, cc, 0.0f);   // plain store, no contention
        __threadfence();
        const unsigned v = atomicAdd(&g_count, 1u);           // the ONLY contended atomic
        is_last = (v == (unsigned)(BLOCKS - 1));
    }
    __syncthreads();

    // ---- last block: reduce the 100 partials in fp64, write out, reset counter ----
    if (is_last) {
        __threadfence();   // acquire: observe all blocks' g_part stores

        double bb = 0.0, oo = 0.0, cc = 0.0;
        if (tid < BLOCKS) {
            const float4 v = g_part[tid];
            bb = (double)v.x; oo = (double)v.y; cc = (double)v.z;
        }
#pragma unroll
        for (int off = 16; off > 0; off >>= 1) {
            bb += __shfl_down_sync(full, bb, off);
            oo += __shfl_down_sync(full, oo, off);
            cc += __shfl_down_sync(full, cc, off);
        }
        __shared__ double d_b[NWARPS], d_o[NWARPS], d_c[NWARPS];
        if (lane == 0) { d_b[warp] = bb; d_o[warp] = oo; d_c[warp] = cc; }
        __syncthreads();
        if (tid == 0) {
            const double Bs = d_b[0] + d_b[1] + d_b[2] + d_b[3];
            const double Os = d_o[0] + d_o[1] + d_o[2] + d_o[3];
            const double Cs = d_c[0] + d_c[1] + d_c[2] + d_c[3];
            const double total = 0.05 * Bs + 1.0 * Os + 0.5 * Cs;
            out[0] = (float)total;
            out[1] = (float)Bs;
            out[2] = (float)Os;
            out[3] = (float)Cs;
            g_count = 0u;      // reset for next graph replay
            __threadfence();
        }
    }
}

extern "C" void kernel_launch(void* const* d_in, const int* in_sizes, int n_in,
                              void* d_out, int out_size)
{
    const float* pred    = (const float*)d_in[0];
    const float* targets = (const float*)d_in[1];
    float* out = (float*)d_out;
    (void)in_sizes; (void)n_in; (void)out_size;

    yolo_loss_kernel<<<BLOCKS, THREADS>>>(pred, targets, out);
}

// round 5
// speedup vs baseline: 1.2149x; 1.0299x over previous
#include <cuda_runtime.h>

// Problem constants (fixed by the dataset)
#define B_   64
#define C_   8
#define H_   256
#define W_   256
#define N_   200
#define NUM_CLASSES 3
#define NTGT (B_ * N_)                 // 12800
#define HW   (H_ * W_)                 // 65536

#define THREADS 256
#define BLOCKS  (NTGT / THREADS)       // 50 (exact) — proven best shape (8 warps/SM)
#define NWARPS  (THREADS / 32)         // 8

// Per-block partials (plain stores, overwritten every launch) + arrival counter
// (reset by last block -> deterministic under graph replay).
__device__ float4 g_part[BLOCKS];
__device__ unsigned int g_count;

__device__ __forceinline__ float softplus_f(float x) {
    // log(1+exp(x)) stable: max(x,0) + log1p(exp(-|x|))  (== jax.nn.softplus)
    return fmaxf(x, 0.0f) + log1pf(expf(-fabsf(x)));
}

__global__ void __launch_bounds__(THREADS)
yolo_loss_kernel(const float* __restrict__ pred,
                 const float* __restrict__ targets,
                 float* __restrict__ out)
{
    const int tid = threadIdx.x;
    const int g   = blockIdx.x * THREADS + tid;    // target index (always < NTGT)

    float bbox_t = 0.0f, obj_t = 0.0f, cls_t = 0.0f;

    {
        const float* t = targets + (size_t)g * 5;
        const float cls_id = __ldg(t + 0);
        const float c0 = __ldg(t + 1), c1 = __ldg(t + 2);
        const float c2 = __ldg(t + 3), c3 = __ldg(t + 4);

        const bool valid = (cls_id >= 0.0f) && ((c0 + c1 + c2 + c3) > 0.0f);
        const int xpix = (int)(c0 * (float)W_);    // fp32 mul then trunc == astype(int32)
        const int ypix = (int)(c1 * (float)H_);
        const bool inb = (xpix >= 0) && (xpix < W_) && (ypix >= 0) && (ypix < H_);

        if (valid && inb) {
            const int xs = min(max(xpix, 0), W_ - 1);
            const int ys = min(max(ypix, 0), H_ - 1);
            const int b  = g / N_;

            const size_t base = (size_t)b * (C_ * HW) + (size_t)ys * W_ + xs;

            // 8 independent scattered loads — batched for MLP=8
            float p[C_];
#pragma unroll
            for (int c = 0; c < C_; c++)
                p[c] = __ldg(pred + base + (size_t)c * HW);

            const float d0 = p[0] - c0, d1 = p[1] - c1, d2 = p[2] - c2, d3 = p[3] - c3;
            bbox_t = 0.25f * (d0 * d0 + d1 * d1 + d2 * d2 + d3 * d3);

            obj_t = softplus_f(p[4]) - p[4];       // bce(p4, 1)

            const int k = (int)fmaxf(cls_id, 0.0f);
            float cs = 0.0f;
#pragma unroll
            for (int j = 0; j < NUM_CLASSES; j++) {
                const float lg = p[5 + j];
                cs += softplus_f(lg) - ((j == k) ? lg : 0.0f);
            }
            cls_t = cs * (1.0f / (float)NUM_CLASSES);
        }
    }

    // ---- block reduction (warp shuffles, then smem across 8 warps) ----
    const unsigned full = 0xFFFFFFFFu;
#pragma unroll
    for (int off = 16; off > 0; off >>= 1) {
        bbox_t += __shfl_down_sync(full, bbox_t, off);
        obj_t  += __shfl_down_sync(full, obj_t,  off);
        cls_t  += __shfl_down_sync(full, cls_t,  off);
    }

    __shared__ float s_b[NWARPS], s_o[NWARPS], s_c[NWARPS];
    const int warp = tid >> 5, lane = tid & 31;
    if (lane == 0) { s_b[warp] = bbox_t; s_o[warp] = obj_t; s_c[warp] = cls_t; }
    __syncthreads();

    __shared__ bool is_last;
    if (tid == 0) {
        float bb = 0.f, oo = 0.f, cc = 0.f;
#pragma unroll
        for (int w = 0; w < NWARPS; w++) { bb += s_b[w]; oo += s_o[w]; cc += s_c[w]; }
        g_part[blockIdx.x] = make_float4(bb, oo, cc, 0.0f);   // plain store — no RMW contention
        __threadfence();
        const unsigned v = atomicAdd(&g_count, 1u);           // the ONLY contended atomic (50 deep)
        is_last = (v == (unsigned)(BLOCKS - 1));
    }
    __syncthreads();

    // ---- last block: reduce the 50 partials in fp64, write out, reset counter ----
    if (is_last) {
        __threadfence();   // acquire: observe all blocks' g_part stores

        double bb = 0.0, oo = 0.0, cc = 0.0;
        if (tid < BLOCKS) {            // 50 < 64 -> first two warps
            const float4 v = g_part[tid];
            bb = (double)v.x; oo = (double)v.y; cc = (double)v.z;
        }
        if (tid < 64) {
#pragma unroll
            for (int off = 16; off > 0; off >>= 1) {
                bb += __shfl_down_sync(full, bb, off);
                oo += __shfl_down_sync(full, oo, off);
                cc += __shfl_down_sync(full, cc, off);
            }
        }
        __shared__ double d_b[2], d_o[2], d_c[2];
        if (tid < 64 && lane == 0) { d_b[warp] = bb; d_o[warp] = oo; d_c[warp] = cc; }
        __syncthreads();
        if (tid == 0) {
            const double Bs = d_b[0] + d_b[1];
            const double Os = d_o[0] + d_o[1];
            const double Cs = d_c[0] + d_c[1];
            const double total = 0.05 * Bs + 1.0 * Os + 0.5 * Cs;
            out[0] = (float)total;
            out[1] = (float)Bs;
            out[2] = (float)Os;
            out[3] = (float)Cs;
            g_count = 0u;      // reset for next graph replay
            __threadfence();
        }
    }
}

extern "C" void kernel_launch(void* const* d_in, const int* in_sizes, int n_in,
                              void* d_out, int out_size)
{
    const float* pred    = (const float*)d_in[0];
    const float* targets = (const float*)d_in[1];
    float* out = (float*)d_out;
    (void)in_sizes; (void)n_in; (void)out_size;

    yolo_loss_kernel<<<BLOCKS, THREADS>>>(pred, targets, out);
}

// round 7
// speedup vs baseline: 1.4132x; 1.1632x over previous
#include <cuda_runtime.h>

// Problem constants (fixed by the dataset)
#define B_   64
#define C_   8
#define H_   256
#define W_   256
#define N_   200
#define NUM_CLASSES 3
#define NTGT (B_ * N_)                 // 12800
#define HW   (H_ * W_)                 // 65536

#define THREADS 256
#define BLOCKS  (NTGT * 2 / THREADS)   // 100 (2 threads per target)
#define NWARPS  (THREADS / 32)         // 8

// Grid-wide accumulators — R1's proven tail: fp64 REDs + counter, last block
// finalizes and resets (deterministic under graph replay).
__device__ double g_acc[3];
__device__ unsigned int g_count;

__device__ __forceinline__ float softplus_f(float x) {
    // log(1+exp(x)) stable: max(x,0) + log1p(exp(-|x|))  (== jax.nn.softplus)
    return fmaxf(x, 0.0f) + log1pf(expf(-fabsf(x)));
}

__global__ void __launch_bounds__(THREADS)
yolo_loss_kernel(const float* __restrict__ pred,
                 const float* __restrict__ targets,
                 float* __restrict__ out)
{
    const int tid = threadIdx.x;
    const int t   = blockIdx.x * THREADS + tid;    // 0 .. 25599
    const int g   = t >> 1;                        // target index
    const int h   = t & 1;                         // half: 0 -> ch 0..3, 1 -> ch 4..7

    float bbox_t = 0.0f, obj_t = 0.0f, cls_t = 0.0f;

    {
        const float* tp = targets + (size_t)g * 5;
        const float cls_id = __ldg(tp + 0);
        const float c0 = __ldg(tp + 1), c1 = __ldg(tp + 2);
        const float c2 = __ldg(tp + 3), c3 = __ldg(tp + 4);

        const bool valid = (cls_id >= 0.0f) && ((c0 + c1 + c2 + c3) > 0.0f);
        const int xpix = (int)(c0 * (float)W_);    // fp32 mul then trunc == astype(int32)
        const int ypix = (int)(c1 * (float)H_);
        const bool inb = (xpix >= 0) && (xpix < W_) && (ypix >= 0) && (ypix < H_);

        if (valid && inb) {
            const int xs = min(max(xpix, 0), W_ - 1);
            const int ys = min(max(ypix, 0), H_ - 1);
            const int b  = g / N_;

            const size_t base = (size_t)b * (C_ * HW) + (size_t)ys * W_ + xs
                              + (size_t)(h * 4) * HW;

            // 4 independent scattered loads per thread (MLP=4),
            // 2 threads/target -> 8 lines in flight per target, 100 SMs active.
            float p[4];
#pragma unroll
            for (int c = 0; c < 4; c++)
                p[c] = __ldg(pred + base + (size_t)c * HW);

            if (h == 0) {
                // bbox: mean squared error over channels 0..3 vs coords
                const float d0 = p[0] - c0, d1 = p[1] - c1;
                const float d2 = p[2] - c2, d3 = p[3] - c3;
                bbox_t = 0.25f * (d0 * d0 + d1 * d1 + d2 * d2 + d3 * d3);
            } else {
                // objectness: bce(p4, 1)
                obj_t = softplus_f(p[0]) - p[0];
                // classification: mean over 3 classes of bce(p[5+j], onehot_j)
                const int k = (int)fmaxf(cls_id, 0.0f);
                float cs = 0.0f;
#pragma unroll
                for (int j = 0; j < NUM_CLASSES; j++) {
                    const float lg = p[1 + j];
                    cs += softplus_f(lg) - ((j == k) ? lg : 0.0f);
                }
                cls_t = cs * (1.0f / (float)NUM_CLASSES);
            }
        }
    }

    // ---- block reduction (warp shuffles, then smem across 8 warps) ----
    const unsigned full = 0xFFFFFFFFu;
#pragma unroll
    for (int off = 16; off > 0; off >>= 1) {
        bbox_t += __shfl_down_sync(full, bbox_t, off);
        obj_t  += __shfl_down_sync(full, obj_t,  off);
        cls_t  += __shfl_down_sync(full, cls_t,  off);
    }

    __shared__ float s_b[NWARPS], s_o[NWARPS], s_c[NWARPS];
    const int warp = tid >> 5, lane = tid & 31;
    if (lane == 0) { s_b[warp] = bbox_t; s_o[warp] = obj_t; s_c[warp] = cls_t; }
    __syncthreads();

    __shared__ bool is_last;
    if (tid == 0) {
        float bb = 0.f, oo = 0.f, cc = 0.f;
#pragma unroll
        for (int w = 0; w < NWARPS; w++) { bb += s_b[w]; oo += s_o[w]; cc += s_c[w]; }

        atomicAdd(&g_acc[0], (double)bb);   // return unused -> RED (fire-and-forget)
        atomicAdd(&g_acc[1], (double)oo);
        atomicAdd(&g_acc[2], (double)cc);
        __threadfence();
        const unsigned v = atomicAdd(&g_count, 1u);
        is_last = (v == (unsigned)(BLOCKS - 1));
    }
    __syncthreads();

    // ---- last block finalizes and resets scratch for the next graph replay ----
    if (is_last && tid == 0) {
        __threadfence();   // observe all blocks' atomics
        const double bs = g_acc[0], os = g_acc[1], cs = g_acc[2];
        const double total = 0.05 * bs + 1.0 * os + 0.5 * cs;
        out[0] = (float)total;
        out[1] = (float)bs;
        out[2] = (float)os;
        out[3] = (float)cs;
        g_acc[0] = 0.0; g_acc[1] = 0.0; g_acc[2] = 0.0;
        g_count = 0u;
        __threadfence();
    }
}

extern "C" void kernel_launch(void* const* d_in, const int* in_sizes, int n_in,
                              void* d_out, int out_size)
{
    const float* pred    = (const float*)d_in[0];
    const float* targets = (const float*)d_in[1];
    float* out = (float*)d_out;
    (void)in_sizes; (void)n_in; (void)out_size;

    yolo_loss_kernel<<<BLOCKS, THREADS>>>(pred, targets, out);
}